// round 10
// baseline (speedup 1.0000x reference)
#include <cuda_runtime.h>
#include <cuda_bf16.h>
#include <cstdint>

#define FDIM 128
#define CDIM 132
#define KBE  136          // padded K in bf16 elements
#define RSTR 272          // bytes per smem row (136 bf16)
#define TILE 128
#define NTHR 128

// smem byte offsets
#define SM_BS   0                          // bias: 136 floats
#define SM_B1S  1024                       // b1 buffer: 128 x 4 floats
#define SM_YH   4096
#define SM_YL   (SM_YH + TILE * RSTR)      // 38912
#define SM_WH   (SM_YL + TILE * RSTR)      // 73728
#define SM_WL   (SM_WH + KBE * RSTR)       // 110720
#define SMEM_BYTES (SM_WL + KBE * RSTR)    // 147712

static __device__ __forceinline__ uint32_t smem_u32(const void* p) {
    uint32_t a;
    asm("{ .reg .u64 t; cvta.to.shared.u64 t, %1; cvt.u32.u64 %0, t; }" : "=r"(a) : "l"(p));
    return a;
}
static __device__ __forceinline__ void split(float v, unsigned short& h, unsigned short& l) {
    __nv_bfloat16 hb = __float2bfloat16(v);
    float r = v - __bfloat162float(hb);
    __nv_bfloat16 lb = __float2bfloat16(r);
    h = __bfloat16_as_ushort(hb);
    l = __bfloat16_as_ushort(lb);
}
// packed split: a -> lower half, b -> upper half
static __device__ __forceinline__ void sp2(float a, float b, uint32_t& h, uint32_t& l) {
    uint32_t hp;
    asm("cvt.rn.bf16x2.f32 %0, %1, %2;" : "=r"(hp) : "f"(b), "f"(a));
    float ha = __uint_as_float(hp << 16);
    float hb = __uint_as_float(hp & 0xFFFF0000u);
    float la = a - ha;
    float lb = b - hb;
    uint32_t lp;
    asm("cvt.rn.bf16x2.f32 %0, %1, %2;" : "=r"(lp) : "f"(lb), "f"(la));
    h = hp; l = lp;
}

static __device__ __forceinline__ void ldsm4(uint32_t a, uint32_t* r) {
    asm volatile("ldmatrix.sync.aligned.m8n8.x4.shared.b16 {%0,%1,%2,%3}, [%4];"
        : "=r"(r[0]), "=r"(r[1]), "=r"(r[2]), "=r"(r[3]) : "r"(a));
}
static __device__ __forceinline__ void ldsm2(uint32_t a, uint32_t* r) {
    asm volatile("ldmatrix.sync.aligned.m8n8.x2.shared.b16 {%0,%1}, [%2];"
        : "=r"(r[0]), "=r"(r[1]) : "r"(a));
}
static __device__ __forceinline__ void ldsm1(uint32_t a, uint32_t* r) {
    asm volatile("ldmatrix.sync.aligned.m8n8.x1.shared.b16 {%0}, [%1];"
        : "=r"(r[0]) : "r"(a));
}
static __device__ __forceinline__ void mma16(float* c, const uint32_t* A, const uint32_t* B) {
    asm volatile("mma.sync.aligned.m16n8k16.row.col.f32.bf16.bf16.f32 "
        "{%0,%1,%2,%3}, {%4,%5,%6,%7}, {%8,%9}, {%0,%1,%2,%3};"
        : "+f"(c[0]), "+f"(c[1]), "+f"(c[2]), "+f"(c[3])
        : "r"(A[0]), "r"(A[1]), "r"(A[2]), "r"(A[3]), "r"(B[0]), "r"(B[1]));
}
static __device__ __forceinline__ void mma8(float* c, const uint32_t* A, uint32_t B) {
    asm volatile("mma.sync.aligned.m16n8k8.row.col.f32.bf16.bf16.f32 "
        "{%0,%1,%2,%3}, {%4,%5}, {%6}, {%0,%1,%2,%3};"
        : "+f"(c[0]), "+f"(c[1]), "+f"(c[2]), "+f"(c[3])
        : "r"(A[0]), "r"(A[1]), "r"(B));
}

struct Offs {
    uint32_t aoff;       // A k16 x4 base (frag f adds f*16*RSTR)
    uint32_t a8off;      // A k8 packed x4 base (frags 0,1; +32*RSTR for 2,3)
    uint32_t bpo[4];     // B x4 pair offsets (k16)
    uint32_t b16s;       // B x2 single-group offset (k16, last group, NG odd)
    uint32_t b8po[4];    // B x2 pair offsets (k8 tail)
    uint32_t b8s;        // B x1 single-group offset (k8 tail, NG odd)
};

// One k16 step: load A (4 frags, hi+lo) + B (NG groups, hi+lo), issue 3 products.
template<int NG>
static __device__ __forceinline__ void k16_step(
    int s, uint32_t yhb, uint32_t ylb, uint32_t whb, uint32_t wlb,
    const Offs& o, float (*acc)[4])
{
    const uint32_t kb = (uint32_t)s * 32;
    uint32_t Ah[4][4], Al[4][4];
    #pragma unroll
    for (int f = 0; f < 4; ++f) {
        ldsm4(yhb + o.aoff + f * (16 * RSTR) + kb, Ah[f]);
        ldsm4(ylb + o.aoff + f * (16 * RSTR) + kb, Al[f]);
    }
    uint32_t Bh[NG][2], Bl[NG][2];
    #pragma unroll
    for (int p = 0; p < NG / 2; ++p) {
        uint32_t r[4];
        ldsm4(whb + o.bpo[p] + kb, r);
        Bh[2*p][0] = r[0]; Bh[2*p][1] = r[1];
        Bh[2*p+1][0] = r[2]; Bh[2*p+1][1] = r[3];
        ldsm4(wlb + o.bpo[p] + kb, r);
        Bl[2*p][0] = r[0]; Bl[2*p][1] = r[1];
        Bl[2*p+1][0] = r[2]; Bl[2*p+1][1] = r[3];
    }
    if (NG & 1) {
        ldsm2(whb + o.b16s + kb, Bh[NG-1]);
        ldsm2(wlb + o.b16s + kb, Bl[NG-1]);
    }
    #pragma unroll
    for (int f = 0; f < 4; ++f) {
        #pragma unroll
        for (int g = 0; g < NG; ++g)
            mma16(acc[f * NG + g], Ah[f], Bh[g]);
    }
    #pragma unroll
    for (int f = 0; f < 4; ++f) {
        #pragma unroll
        for (int g = 0; g < NG; ++g)
            mma16(acc[f * NG + g], Ah[f], Bl[g]);
    }
    #pragma unroll
    for (int f = 0; f < 4; ++f) {
        #pragma unroll
        for (int g = 0; g < NG; ++g)
            mma16(acc[f * NG + g], Al[f], Bh[g]);
    }
}

template<int CW>
static __device__ __forceinline__ void compute_tile(
    uint32_t yhb, uint32_t ylb, uint32_t whb, uint32_t wlb,
    const Offs& o, const float* bs, float* b1s,
    float* __restrict__ a1, long long row0, long long n,
    int mrow, int qr, int qc)
{
    constexpr int NG = CW ? 8 : 9;
    constexpr int G0 = CW ? 9 : 0;

    float acc[4 * NG][4];
    #pragma unroll
    for (int i = 0; i < 4 * NG; ++i)
        #pragma unroll
        for (int j = 0; j < 4; ++j) acc[i][j] = 0.f;

    #pragma unroll
    for (int s = 0; s < 8; ++s)
        k16_step<NG>(s, yhb, ylb, whb, wlb, o, acc);

    // ---- k8 tail: k = 128..135 (packed 2 frags per x4) ----
    {
        uint32_t Ah[4][2], Al[4][2];
        {
            uint32_t r[4];
            ldsm4(yhb + o.a8off, r);
            Ah[0][0] = r[0]; Ah[0][1] = r[1]; Ah[1][0] = r[2]; Ah[1][1] = r[3];
            ldsm4(yhb + o.a8off + 32 * RSTR, r);
            Ah[2][0] = r[0]; Ah[2][1] = r[1]; Ah[3][0] = r[2]; Ah[3][1] = r[3];
            ldsm4(ylb + o.a8off, r);
            Al[0][0] = r[0]; Al[0][1] = r[1]; Al[1][0] = r[2]; Al[1][1] = r[3];
            ldsm4(ylb + o.a8off + 32 * RSTR, r);
            Al[2][0] = r[0]; Al[2][1] = r[1]; Al[3][0] = r[2]; Al[3][1] = r[3];
        }
        uint32_t B8h[NG], B8l[NG];
        #pragma unroll
        for (int p = 0; p < NG / 2; ++p) {
            uint32_t r[2];
            ldsm2(whb + o.b8po[p], r);
            B8h[2*p] = r[0]; B8h[2*p+1] = r[1];
            ldsm2(wlb + o.b8po[p], r);
            B8l[2*p] = r[0]; B8l[2*p+1] = r[1];
        }
        if (NG & 1) {
            uint32_t r[1];
            ldsm1(whb + o.b8s, r); B8h[NG-1] = r[0];
            ldsm1(wlb + o.b8s, r); B8l[NG-1] = r[0];
        }
        #pragma unroll
        for (int f = 0; f < 4; ++f) {
            #pragma unroll
            for (int g = 0; g < NG; ++g) {
                mma8(acc[f * NG + g], Ah[f], B8h[g]);
                mma8(acc[f * NG + g], Ah[f], B8l[g]);
                mma8(acc[f * NG + g], Al[f], B8h[g]);
            }
        }
    }

    // ---- epilogue ----
    #pragma unroll
    for (int f = 0; f < 4; ++f) {
        #pragma unroll
        for (int g = 0; g < NG; ++g) {
            const int ga = G0 + g;
            const float* ac = acc[f * NG + g];
            const int colg = ga * 8 + qc * 2;
            if (ga < 16) {
                float bx = bs[colg], by = bs[colg + 1];
                long long r1 = row0 + mrow + f * 16 + qr;
                if (r1 < n)
                    *(float2*)(a1 + r1 * FDIM + colg) = make_float2(ac[0] + bx, ac[1] + by);
                if (r1 + 8 < n)
                    *(float2*)(a1 + (r1 + 8) * FDIM + colg) = make_float2(ac[2] + bx, ac[3] + by);
            } else if (ga == 16) {
                if (qc < 2) {
                    int l = qc * 2;
                    float bx = bs[FDIM + l], by = bs[FDIM + l + 1];
                    int rl = mrow + f * 16 + qr;
                    b1s[rl * 4 + l]       = ac[0] + bx;
                    b1s[rl * 4 + l + 1]   = ac[1] + by;
                    b1s[(rl + 8) * 4 + l]     = ac[2] + bx;
                    b1s[(rl + 8) * 4 + l + 1] = ac[3] + by;
                }
            }
        }
    }
}

// stage one 64-row segment of y (x part + d_chi); thread covers row (r2), half hh
static __device__ __forceinline__ void stage_seg(
    const float* __restrict__ x, const float* __restrict__ chi,
    char* sm, long long row, bool ok, int rloc, int hh, float* cvx)
{
    {
        const float* xp = x + row * FDIM + hh * 64;
        unsigned short* dsth = (unsigned short*)(sm + SM_YH) + rloc * KBE + hh * 64;
        unsigned short* dstl = (unsigned short*)(sm + SM_YL) + rloc * KBE + hh * 64;
        #pragma unroll
        for (int c = 0; c < 8; ++c) {
            float4 va = ok ? *(const float4*)(xp + c * 8)     : make_float4(0, 0, 0, 0);
            float4 vb = ok ? *(const float4*)(xp + c * 8 + 4) : make_float4(0, 0, 0, 0);
            uint4 hv, lv;
            sp2(va.x, va.y, hv.x, lv.x);
            sp2(va.z, va.w, hv.y, lv.y);
            sp2(vb.x, vb.y, hv.z, lv.z);
            sp2(vb.z, vb.w, hv.w, lv.w);
            *(uint4*)(dsth + c * 8) = hv;
            *(uint4*)(dstl + c * 8) = lv;
        }
    }
    {
        const float4* cp = (const float4*)(chi + row * 16 + hh * 8);
        float4 ca = ok ? cp[0] : make_float4(0, 0, 0, 0);
        float4 cb = ok ? cp[1] : make_float4(0, 0, 0, 0);
        cvx[0] = ca.x; cvx[1] = ca.y; cvx[2] = ca.z; cvx[3] = ca.w;
        cvx[4] = cb.x; cvx[5] = cb.y; cvx[6] = cb.z; cvx[7] = cb.w;

        float qa = ca.x * ca.x;
        float qb = ca.y * ca.y + ca.z * ca.z + ca.w * ca.w;
        float qc2 = cb.x * cb.x + cb.y * cb.y + cb.z * cb.z + cb.w * cb.w;
        float s0, s1, s2, s3;
        if (hh == 0) { s0 = qa;  s1 = qb;  s2 = qc2; s3 = 0.f; }
        else         { s0 = 0.f; s1 = 0.f; s2 = qa;  s3 = qb + qc2; }
        s0 += __shfl_xor_sync(0xFFFFFFFFu, s0, 1);
        s1 += __shfl_xor_sync(0xFFFFFFFFu, s1, 1);
        s2 += __shfl_xor_sync(0xFFFFFFFFu, s2, 1);
        s3 += __shfl_xor_sync(0xFFFFFFFFu, s3, 1);

        uint32_t h0, l0, h1, l1;
        sp2(s0, s1, h0, l0);
        sp2(s2, s3, h1, l1);
        if (hh == 0)
            *(uint4*)(sm + SM_YH + rloc * RSTR + 256) = make_uint4(h0, h1, 0u, 0u);
        else
            *(uint4*)(sm + SM_YL + rloc * RSTR + 256) = make_uint4(l0, l1, 0u, 0u);
    }
}

static __device__ __forceinline__ void chi_out_store(
    float* __restrict__ co, const float* b1s, const float* cvx,
    long long row, bool ok, int rloc, int hh)
{
    if (!ok) return;
    float4 bv = ((const float4*)b1s)[rloc];
    float o8[8];
    if (hh == 0) {
        o8[0] = bv.x * cvx[0];
        o8[1] = bv.y * cvx[1]; o8[2] = bv.y * cvx[2]; o8[3] = bv.y * cvx[3];
        o8[4] = bv.z * cvx[4]; o8[5] = bv.z * cvx[5];
        o8[6] = bv.z * cvx[6]; o8[7] = bv.z * cvx[7];
    } else {
        o8[0] = bv.z * cvx[0];
        #pragma unroll
        for (int m = 1; m < 8; ++m) o8[m] = bv.w * cvx[m];
    }
    float4* dst = (float4*)(co + row * 16 + hh * 8);
    dst[0] = make_float4(o8[0], o8[1], o8[2], o8[3]);
    dst[1] = make_float4(o8[4], o8[5], o8[6], o8[7]);
}

__global__ void __launch_bounds__(NTHR, 1)
ib_mma(const float* __restrict__ x, const float* __restrict__ chi,
       const float* __restrict__ W, const float* __restrict__ b,
       float* __restrict__ a1, float* __restrict__ co,
       long long n, long long T)
{
    extern __shared__ char sm[];
    float* bs  = (float*)(sm + SM_BS);
    float* b1s = (float*)(sm + SM_B1S);
    unsigned short* whp = (unsigned short*)(sm + SM_WH);
    unsigned short* wlp = (unsigned short*)(sm + SM_WL);

    const int tid = threadIdx.x, wid = tid >> 5, lane = tid & 31;
    const uint32_t smb = smem_u32(sm);
    const uint32_t yhb = smb + SM_YH, ylb = smb + SM_YL;
    const uint32_t whb = smb + SM_WH, wlb = smb + SM_WL;

    // ---- stage W^T (hi/lo bf16) + bias, once ----
    for (int i = tid; i < KBE * KBE; i += NTHR) {
        int nn = i % KBE, kk = i / KBE;
        float w = (nn < CDIM && kk < CDIM) ? W[kk * CDIM + nn] : 0.f;
        unsigned short h, l;
        split(w, h, l);
        whp[nn * KBE + kk] = h;
        wlp[nn * KBE + kk] = l;
    }
    for (int i = tid; i < KBE; i += NTHR) bs[i] = (i < CDIM) ? b[i] : 0.f;

    // ---- per-warp ldmatrix offsets (2M x 2N warp grid) ----
    const int mrow = (wid & 1) * 64;
    const int cw   = wid >> 1;               // 0: groups 0..8, 1: groups 9..16
    const int j3 = lane >> 3, rw = lane & 7;
    const int qr = lane >> 2, qc = lane & 3;
    const int g0 = cw ? 9 : 0;

    Offs o;
    o.aoff  = (uint32_t)((mrow + ((j3 & 1) << 3) + rw) * RSTR + ((j3 >> 1) << 4));
    o.a8off = (uint32_t)((mrow + j3 * 8 + rw) * RSTR + 256);
    #pragma unroll
    for (int p = 0; p < 4; ++p) {
        int g = g0 + 2 * p;
        o.bpo[p]  = (uint32_t)((g * 8 + ((j3 >> 1) << 3) + rw) * RSTR + ((j3 & 1) << 4));
        o.b8po[p] = (uint32_t)((g * 8 + ((j3 & 1) << 3) + rw) * RSTR + 256);
    }
    o.b16s = (uint32_t)((64 + rw) * RSTR + ((j3 & 1) << 4));
    o.b8s  = (uint32_t)((64 + rw) * RSTR + 256);

    const int r2 = tid >> 1, hh = tid & 1;
    const int grid = gridDim.x;

    // ---- preamble: stage first tile (2 segments of 64 rows) ----
    float cvx[2][8];
    {
        long long row0 = blockIdx.x * (long long)TILE;
        #pragma unroll
        for (int seg = 0; seg < 2; ++seg) {
            long long row = row0 + seg * 64 + r2;
            stage_seg(x, chi, sm, row, (blockIdx.x < T) && (row < n),
                      seg * 64 + r2, hh, cvx[seg]);
        }
    }
    __syncthreads();

    for (long long t = blockIdx.x; t < T; t += grid) {
        const long long row0 = t * TILE;

        // ---- MMA + a1/b1 epilogue ----
        if (cw == 0)
            compute_tile<0>(yhb, ylb, whb, wlb, o, bs, b1s, a1, row0, n, mrow, qr, qc);
        else
            compute_tile<1>(yhb, ylb, whb, wlb, o, bs, b1s, a1, row0, n, mrow, qr, qc);
        __syncthreads();

        // ---- overlap: stage(t+grid) + chi_out(t) ----
        const long long t2 = t + grid;
        float cvn[2][8];
        #pragma unroll
        for (int seg = 0; seg < 2; ++seg) {
            if (t2 < T) {
                long long row2 = t2 * TILE + seg * 64 + r2;
                stage_seg(x, chi, sm, row2, row2 < n, seg * 64 + r2, hh, cvn[seg]);
            }
            long long rowc = row0 + seg * 64 + r2;
            chi_out_store(co, b1s, cvx[seg], rowc, rowc < n, seg * 64 + r2, hh);
        }
        #pragma unroll
        for (int seg = 0; seg < 2; ++seg)
            #pragma unroll
            for (int m = 0; m < 8; ++m) cvx[seg][m] = cvn[seg][m];
        __syncthreads();
    }
}

extern "C" void kernel_launch(void* const* d_in, const int* in_sizes, int n_in,
                              void* d_out, int out_size)
{
    int ix = 0, ichi = 1, iW = 3, ib_ = 4;
    long long maxsz = -1;
    for (int i = 0; i < n_in; ++i)
        if ((long long)in_sizes[i] > maxsz) { maxsz = in_sizes[i]; ix = i; }
    long long n = maxsz / FDIM;
    for (int i = 0; i < n_in; ++i) {
        long long s = in_sizes[i];
        if (i == ix) continue;
        if (s == CDIM * CDIM) iW = i;
        else if (s == CDIM)   ib_ = i;
        else if (s == 16 * n) ichi = i;
    }
    const float* x   = (const float*)d_in[ix];
    const float* chi = (const float*)d_in[ichi];
    const float* W   = (const float*)d_in[iW];
    const float* b   = (const float*)d_in[ib_];
    float* a1 = (float*)d_out;
    float* co = a1 + (size_t)n * FDIM;

    long long T = (n + TILE - 1) / TILE;
    int sms = 148;
    cudaDeviceGetAttribute(&sms, cudaDevAttrMultiProcessorCount, 0);
    int grid = (int)(T < sms ? T : sms);

    cudaFuncSetAttribute(ib_mma, cudaFuncAttributeMaxDynamicSharedMemorySize, SMEM_BYTES);
    ib_mma<<<grid, NTHR, SMEM_BYTES>>>(x, chi, W, b, a1, co, n, T);
}

// round 11
// speedup vs baseline: 1.0360x; 1.0360x over previous
#include <cuda_runtime.h>
#include <cuda_bf16.h>
#include <cstdint>

#define FDIM 128
#define CDIM 132
#define KBE  136          // padded K in bf16 elements
#define RSTR 272          // bytes per smem row (136 bf16)
#define TILE 128
#define NTHR 256

// smem byte offsets
#define SM_BS   0                           // bias: 136 floats
#define SM_B1S  1024                        // b1 double buffer: 2 x (128 x 4 floats)
#define SM_Y    8192                        // y double buffer: 2 x (hi 34816 + lo 34816)
#define YBUF    69632
#define YLOFF   34816
#define SM_WH   (SM_Y + 2 * YBUF)           // 147456
#define SM_WL   (SM_WH + KBE * RSTR)        // 184448
#define SMEM_BYTES (SM_WL + KBE * RSTR)     // 221440

static __device__ __forceinline__ uint32_t smem_u32(const void* p) {
    uint32_t a;
    asm("{ .reg .u64 t; cvta.to.shared.u64 t, %1; cvt.u32.u64 %0, t; }" : "=r"(a) : "l"(p));
    return a;
}
static __device__ __forceinline__ void split(float v, unsigned short& h, unsigned short& l) {
    __nv_bfloat16 hb = __float2bfloat16(v);
    float r = v - __bfloat162float(hb);
    __nv_bfloat16 lb = __float2bfloat16(r);
    h = __bfloat16_as_ushort(hb);
    l = __bfloat16_as_ushort(lb);
}
// packed split: a -> lower half, b -> upper half
static __device__ __forceinline__ void sp2(float a, float b, uint32_t& h, uint32_t& l) {
    uint32_t hp;
    asm("cvt.rn.bf16x2.f32 %0, %1, %2;" : "=r"(hp) : "f"(b), "f"(a));
    float ha = __uint_as_float(hp << 16);
    float hb = __uint_as_float(hp & 0xFFFF0000u);
    float la = a - ha;
    float lb = b - hb;
    uint32_t lp;
    asm("cvt.rn.bf16x2.f32 %0, %1, %2;" : "=r"(lp) : "f"(lb), "f"(la));
    h = hp; l = lp;
}

static __device__ __forceinline__ void ldsm4(uint32_t a, uint32_t* r) {
    asm volatile("ldmatrix.sync.aligned.m8n8.x4.shared.b16 {%0,%1,%2,%3}, [%4];"
        : "=r"(r[0]), "=r"(r[1]), "=r"(r[2]), "=r"(r[3]) : "r"(a));
}
static __device__ __forceinline__ void ldsm2(uint32_t a, uint32_t* r) {
    asm volatile("ldmatrix.sync.aligned.m8n8.x2.shared.b16 {%0,%1}, [%2];"
        : "=r"(r[0]), "=r"(r[1]) : "r"(a));
}
static __device__ __forceinline__ void ldsm1(uint32_t a, uint32_t* r) {
    asm volatile("ldmatrix.sync.aligned.m8n8.x1.shared.b16 {%0}, [%1];"
        : "=r"(r[0]) : "r"(a));
}
static __device__ __forceinline__ void mma16(float* c, const uint32_t* A, const uint32_t* B) {
    asm volatile("mma.sync.aligned.m16n8k16.row.col.f32.bf16.bf16.f32 "
        "{%0,%1,%2,%3}, {%4,%5,%6,%7}, {%8,%9}, {%0,%1,%2,%3};"
        : "+f"(c[0]), "+f"(c[1]), "+f"(c[2]), "+f"(c[3])
        : "r"(A[0]), "r"(A[1]), "r"(A[2]), "r"(A[3]), "r"(B[0]), "r"(B[1]));
}
static __device__ __forceinline__ void mma8(float* c, const uint32_t* A, uint32_t B) {
    asm volatile("mma.sync.aligned.m16n8k8.row.col.f32.bf16.bf16.f32 "
        "{%0,%1,%2,%3}, {%4,%5}, {%6}, {%0,%1,%2,%3};"
        : "+f"(c[0]), "+f"(c[1]), "+f"(c[2]), "+f"(c[3])
        : "r"(A[0]), "r"(A[1]), "r"(B));
}

struct Offs {
    uint32_t aoff;
    uint32_t bpo[4];
    uint32_t b16s;
    uint32_t b8po[4];
    uint32_t b8s;
};

template<int NG> struct Frag {
    uint32_t Ah0[4], Ah1[4], Al0[4], Al1[4];
    uint32_t Bh[NG][2], Bl[NG][2];
};

template<int NG>
static __device__ __forceinline__ void load_frag(
    int s, uint32_t yhb, uint32_t ylb, uint32_t whb, uint32_t wlb,
    const Offs& o, Frag<NG>& F)
{
    const uint32_t kb = (uint32_t)s * 32;
    ldsm4(yhb + o.aoff + kb, F.Ah0);
    ldsm4(yhb + o.aoff + 4352 + kb, F.Ah1);
    ldsm4(ylb + o.aoff + kb, F.Al0);
    ldsm4(ylb + o.aoff + 4352 + kb, F.Al1);
    #pragma unroll
    for (int p = 0; p < NG / 2; ++p) {
        uint32_t r[4];
        ldsm4(whb + o.bpo[p] + kb, r);
        F.Bh[2*p][0] = r[0]; F.Bh[2*p][1] = r[1];
        F.Bh[2*p+1][0] = r[2]; F.Bh[2*p+1][1] = r[3];
        ldsm4(wlb + o.bpo[p] + kb, r);
        F.Bl[2*p][0] = r[0]; F.Bl[2*p][1] = r[1];
        F.Bl[2*p+1][0] = r[2]; F.Bl[2*p+1][1] = r[3];
    }
    if (NG & 1) {
        ldsm2(whb + o.b16s + kb, F.Bh[NG-1]);
        ldsm2(wlb + o.b16s + kb, F.Bl[NG-1]);
    }
}

template<int NG>
static __device__ __forceinline__ void issue_mma(const Frag<NG>& F, float (*acc)[4])
{
    #pragma unroll
    for (int g = 0; g < NG; ++g) {
        mma16(acc[g],      F.Ah0, F.Bh[g]);
        mma16(acc[NG + g], F.Ah1, F.Bh[g]);
    }
    #pragma unroll
    for (int g = 0; g < NG; ++g) {
        mma16(acc[g],      F.Ah0, F.Bl[g]);
        mma16(acc[NG + g], F.Ah1, F.Bl[g]);
    }
    #pragma unroll
    for (int g = 0; g < NG; ++g) {
        mma16(acc[g],      F.Al0, F.Bh[g]);
        mma16(acc[NG + g], F.Al1, F.Bh[g]);
    }
}

template<int CW>
static __device__ __forceinline__ void compute_tile(
    uint32_t yhb, uint32_t ylb, uint32_t whb, uint32_t wlb,
    const Offs& o, const float* bs, float* b1s,
    float* __restrict__ a1, long long row0, long long n,
    int mrow, int qr, int qc)
{
    constexpr int NG = CW ? 8 : 9;
    constexpr int G0 = CW ? 9 : 0;

    float acc[2 * NG][4];
    #pragma unroll
    for (int i = 0; i < 2 * NG; ++i)
        #pragma unroll
        for (int j = 0; j < 4; ++j) acc[i][j] = 0.f;

    // ---- software-pipelined k16 steps ----
    Frag<NG> f0, f1;
    load_frag<NG>(0, yhb, ylb, whb, wlb, o, f0);
    #pragma unroll
    for (int s = 0; s < 8; s += 2) {
        if (s + 1 < 8) load_frag<NG>(s + 1, yhb, ylb, whb, wlb, o, f1);
        issue_mma<NG>(f0, acc);
        if (s + 2 < 8) load_frag<NG>(s + 2, yhb, ylb, whb, wlb, o, f0);
        if (s + 1 < 8) issue_mma<NG>(f1, acc);
    }

    // ---- k8 tail: k = 128..135 ----
    {
        uint32_t Ah0[2], Ah1[2], Al0[2], Al1[2];
        ldsm2(yhb + o.aoff + 256, Ah0);
        ldsm2(yhb + o.aoff + 4352 + 256, Ah1);
        ldsm2(ylb + o.aoff + 256, Al0);
        ldsm2(ylb + o.aoff + 4352 + 256, Al1);
        uint32_t B8h[NG], B8l[NG];
        #pragma unroll
        for (int p = 0; p < NG / 2; ++p) {
            uint32_t r[2];
            ldsm2(whb + o.b8po[p], r);
            B8h[2*p] = r[0]; B8h[2*p+1] = r[1];
            ldsm2(wlb + o.b8po[p], r);
            B8l[2*p] = r[0]; B8l[2*p+1] = r[1];
        }
        if (NG & 1) {
            uint32_t r[1];
            ldsm1(whb + o.b8s, r); B8h[NG-1] = r[0];
            ldsm1(wlb + o.b8s, r); B8l[NG-1] = r[0];
        }
        #pragma unroll
        for (int g = 0; g < NG; ++g) {
            mma8(acc[g],      Ah0, B8h[g]);
            mma8(acc[NG + g], Ah1, B8h[g]);
            mma8(acc[g],      Ah0, B8l[g]);
            mma8(acc[NG + g], Ah1, B8l[g]);
            mma8(acc[g],      Al0, B8h[g]);
            mma8(acc[NG + g], Al1, B8h[g]);
        }
    }

    // ---- epilogue ----
    #pragma unroll
    for (int f = 0; f < 2; ++f) {
        #pragma unroll
        for (int g = 0; g < NG; ++g) {
            const int ga = G0 + g;
            const float* ac = acc[f * NG + g];
            const int colg = ga * 8 + qc * 2;
            if (ga < 16) {
                float bx = bs[colg], by = bs[colg + 1];
                long long r1 = row0 + mrow + f * 16 + qr;
                if (r1 < n)
                    *(float2*)(a1 + r1 * FDIM + colg) = make_float2(ac[0] + bx, ac[1] + by);
                if (r1 + 8 < n)
                    *(float2*)(a1 + (r1 + 8) * FDIM + colg) = make_float2(ac[2] + bx, ac[3] + by);
            } else if (ga == 16) {
                if (qc < 2) {
                    int l = qc * 2;
                    float bx = bs[FDIM + l], by = bs[FDIM + l + 1];
                    int rl = mrow + f * 16 + qr;
                    b1s[rl * 4 + l]       = ac[0] + bx;
                    b1s[rl * 4 + l + 1]   = ac[1] + by;
                    b1s[(rl + 8) * 4 + l]     = ac[2] + bx;
                    b1s[(rl + 8) * 4 + l + 1] = ac[3] + by;
                }
            }
        }
    }
}

// stage one row of y (x part + d_chi) into buffer with hi at yh_off;
// thread covers row rloc (=tid>>1), half hh (=tid&1)
static __device__ __forceinline__ void stage_seg(
    const float* __restrict__ x, const float* __restrict__ chi,
    char* sm, uint32_t yh_off, long long row, bool ok, int rloc, int hh, float* cvx)
{
    {
        const float* xp = x + row * FDIM + hh * 64;
        unsigned short* dsth = (unsigned short*)(sm + yh_off) + rloc * KBE + hh * 64;
        unsigned short* dstl = (unsigned short*)(sm + yh_off + YLOFF) + rloc * KBE + hh * 64;
        #pragma unroll
        for (int c = 0; c < 8; ++c) {
            float4 va = ok ? *(const float4*)(xp + c * 8)     : make_float4(0, 0, 0, 0);
            float4 vb = ok ? *(const float4*)(xp + c * 8 + 4) : make_float4(0, 0, 0, 0);
            uint4 hv, lv;
            sp2(va.x, va.y, hv.x, lv.x);
            sp2(va.z, va.w, hv.y, lv.y);
            sp2(vb.x, vb.y, hv.z, lv.z);
            sp2(vb.z, vb.w, hv.w, lv.w);
            *(uint4*)(dsth + c * 8) = hv;
            *(uint4*)(dstl + c * 8) = lv;
        }
    }
    {
        const float4* cp = (const float4*)(chi + row * 16 + hh * 8);
        float4 ca = ok ? cp[0] : make_float4(0, 0, 0, 0);
        float4 cb = ok ? cp[1] : make_float4(0, 0, 0, 0);
        cvx[0] = ca.x; cvx[1] = ca.y; cvx[2] = ca.z; cvx[3] = ca.w;
        cvx[4] = cb.x; cvx[5] = cb.y; cvx[6] = cb.z; cvx[7] = cb.w;

        float qa = ca.x * ca.x;
        float qb = ca.y * ca.y + ca.z * ca.z + ca.w * ca.w;
        float qc2 = cb.x * cb.x + cb.y * cb.y + cb.z * cb.z + cb.w * cb.w;
        float s0, s1, s2, s3;
        if (hh == 0) { s0 = qa;  s1 = qb;  s2 = qc2; s3 = 0.f; }
        else         { s0 = 0.f; s1 = 0.f; s2 = qa;  s3 = qb + qc2; }
        s0 += __shfl_xor_sync(0xFFFFFFFFu, s0, 1);
        s1 += __shfl_xor_sync(0xFFFFFFFFu, s1, 1);
        s2 += __shfl_xor_sync(0xFFFFFFFFu, s2, 1);
        s3 += __shfl_xor_sync(0xFFFFFFFFu, s3, 1);

        uint32_t h0, l0, h1, l1;
        sp2(s0, s1, h0, l0);
        sp2(s2, s3, h1, l1);
        if (hh == 0)
            *(uint4*)(sm + yh_off + rloc * RSTR + 256) = make_uint4(h0, h1, 0u, 0u);
        else
            *(uint4*)(sm + yh_off + YLOFF + rloc * RSTR + 256) = make_uint4(l0, l1, 0u, 0u);
    }
}

static __device__ __forceinline__ void chi_out_store(
    float* __restrict__ co, const float* b1s, const float* cvx,
    long long row, bool ok, int rloc, int hh)
{
    if (!ok) return;
    float4 bv = ((const float4*)b1s)[rloc];
    float o8[8];
    if (hh == 0) {
        o8[0] = bv.x * cvx[0];
        o8[1] = bv.y * cvx[1]; o8[2] = bv.y * cvx[2]; o8[3] = bv.y * cvx[3];
        o8[4] = bv.z * cvx[4]; o8[5] = bv.z * cvx[5];
        o8[6] = bv.z * cvx[6]; o8[7] = bv.z * cvx[7];
    } else {
        o8[0] = bv.z * cvx[0];
        #pragma unroll
        for (int m = 1; m < 8; ++m) o8[m] = bv.w * cvx[m];
    }
    float4* dst = (float4*)(co + row * 16 + hh * 8);
    dst[0] = make_float4(o8[0], o8[1], o8[2], o8[3]);
    dst[1] = make_float4(o8[4], o8[5], o8[6], o8[7]);
}

__global__ void __launch_bounds__(NTHR, 1)
ib_mma(const float* __restrict__ x, const float* __restrict__ chi,
       const float* __restrict__ W, const float* __restrict__ b,
       float* __restrict__ a1, float* __restrict__ co,
       long long n, long long T)
{
    extern __shared__ char sm[];
    float* bs  = (float*)(sm + SM_BS);
    unsigned short* whp = (unsigned short*)(sm + SM_WH);
    unsigned short* wlp = (unsigned short*)(sm + SM_WL);

    const int tid = threadIdx.x, wid = tid >> 5, lane = tid & 31;
    const uint32_t smb = smem_u32(sm);
    const uint32_t whb = smb + SM_WH, wlb = smb + SM_WL;

    // ---- stage W^T (hi/lo bf16) + bias, once ----
    for (int i = tid; i < KBE * KBE; i += NTHR) {
        int nn = i % KBE, kk = i / KBE;
        float w = (nn < CDIM && kk < CDIM) ? W[kk * CDIM + nn] : 0.f;
        unsigned short h, l;
        split(w, h, l);
        whp[nn * KBE + kk] = h;
        wlp[nn * KBE + kk] = l;
    }
    for (int i = tid; i < KBE; i += NTHR) bs[i] = (i < CDIM) ? b[i] : 0.f;

    // ---- per-warp ldmatrix offsets (4M x 2N warp grid) ----
    const int mrow = (wid & 3) * 32;
    const int cw   = wid >> 2;               // 0: groups 0..8, 1: groups 9..16
    const int j3 = lane >> 3, rw = lane & 7;
    const int qr = lane >> 2, qc = lane & 3;
    const int g0 = cw ? 9 : 0;

    Offs o;
    o.aoff = (uint32_t)((mrow + ((j3 & 1) << 3) + rw) * RSTR + ((j3 >> 1) << 4));
    #pragma unroll
    for (int p = 0; p < 4; ++p) {
        int g = g0 + 2 * p;
        o.bpo[p]  = (uint32_t)((g * 8 + ((j3 >> 1) << 3) + rw) * RSTR + ((j3 & 1) << 4));
        o.b8po[p] = (uint32_t)((g * 8 + ((j3 & 1) << 3) + rw) * RSTR + 256);
    }
    o.b16s = (uint32_t)((64 + rw) * RSTR + ((j3 & 1) << 4));
    o.b8s  = (uint32_t)((64 + rw) * RSTR + 256);

    const int r2 = tid >> 1, hh = tid & 1;
    const int grid = gridDim.x;

    // ---- preamble: stage first tile into buf 0 ----
    float cva[8], cvb[8];
    {
        long long row = blockIdx.x * (long long)TILE + r2;
        stage_seg(x, chi, sm, SM_Y, row, (blockIdx.x < T) && (row < n), r2, hh, cva);
    }
    __syncthreads();

    int p = 0;
    for (long long t = blockIdx.x; t < T; t += grid) {
        const long long row0 = t * TILE;
        const uint32_t yh = SM_Y + (uint32_t)p * YBUF;
        float* b1s_p = (float*)(sm + SM_B1S + p * 2048);

        // ---- MMA + a1/b1 epilogue (reads buf p, writes b1s[p]) ----
        if (cw == 0)
            compute_tile<0>(smb + yh, smb + yh + YLOFF, whb, wlb, o, bs, b1s_p,
                            a1, row0, n, mrow, qr, qc);
        else
            compute_tile<1>(smb + yh, smb + yh + YLOFF, whb, wlb, o, bs, b1s_p,
                            a1, row0, n, mrow, qr, qc);

        // ---- per-warp (no sync): stage(t+grid) into buf p^1 ----
        const long long t2 = t + grid;
        if (t2 < T) {
            long long row2 = t2 * TILE + r2;
            stage_seg(x, chi, sm, SM_Y + (uint32_t)(p ^ 1) * YBUF,
                      row2, row2 < n, r2, hh, cvb);
        }
        __syncthreads();   // b1s[p] + buf p^1 complete

        // ---- chi_out(t) from b1s[p]; overlaps next tile's compute ----
        chi_out_store(co, b1s_p, cva, row0 + r2, row0 + r2 < n, r2, hh);
        #pragma unroll
        for (int m = 0; m < 8; ++m) cva[m] = cvb[m];
        p ^= 1;
    }
}

extern "C" void kernel_launch(void* const* d_in, const int* in_sizes, int n_in,
                              void* d_out, int out_size)
{
    int ix = 0, ichi = 1, iW = 3, ib_ = 4;
    long long maxsz = -1;
    for (int i = 0; i < n_in; ++i)
        if ((long long)in_sizes[i] > maxsz) { maxsz = in_sizes[i]; ix = i; }
    long long n = maxsz / FDIM;
    for (int i = 0; i < n_in; ++i) {
        long long s = in_sizes[i];
        if (i == ix) continue;
        if (s == CDIM * CDIM) iW = i;
        else if (s == CDIM)   ib_ = i;
        else if (s == 16 * n) ichi = i;
    }
    const float* x   = (const float*)d_in[ix];
    const float* chi = (const float*)d_in[ichi];
    const float* W   = (const float*)d_in[iW];
    const float* b   = (const float*)d_in[ib_];
    float* a1 = (float*)d_out;
    float* co = a1 + (size_t)n * FDIM;

    long long T = (n + TILE - 1) / TILE;
    int sms = 148;
    cudaDeviceGetAttribute(&sms, cudaDevAttrMultiProcessorCount, 0);
    int grid = (int)(T < sms ? T : sms);

    cudaFuncSetAttribute(ib_mma, cudaFuncAttributeMaxDynamicSharedMemorySize, SMEM_BYTES);
    ib_mma<<<grid, NTHR, SMEM_BYTES>>>(x, chi, W, b, a1, co, n, T);
}

// round 12
// speedup vs baseline: 1.0743x; 1.0369x over previous
#include <cuda_runtime.h>
#include <cuda_bf16.h>
#include <cstdint>

#define FDIM 128
#define CDIM 132
#define KBE  136          // padded K in bf16 elements
#define RSTR 272          // bytes per smem row (136 bf16)
#define TILE 256
#define NTHR 256

// smem byte offsets
#define SM_BS   0                           // bias: 136 floats
#define SM_B1S  1024                        // b1 buffer: 256 x 4 floats = 4096
#define SM_YH   8192
#define SM_YL   (SM_YH + TILE * RSTR)       // 77824
#define SM_WH   (SM_YL + TILE * RSTR)       // 147456
#define SM_WL   (SM_WH + KBE * RSTR)        // 184448
#define SMEM_BYTES (SM_WL + KBE * RSTR)     // 221440

static __device__ __forceinline__ uint32_t smem_u32(const void* p) {
    uint32_t a;
    asm("{ .reg .u64 t; cvta.to.shared.u64 t, %1; cvt.u32.u64 %0, t; }" : "=r"(a) : "l"(p));
    return a;
}
static __device__ __forceinline__ void split(float v, unsigned short& h, unsigned short& l) {
    __nv_bfloat16 hb = __float2bfloat16(v);
    float r = v - __bfloat162float(hb);
    __nv_bfloat16 lb = __float2bfloat16(r);
    h = __bfloat16_as_ushort(hb);
    l = __bfloat16_as_ushort(lb);
}
// packed split: a -> lower half, b -> upper half
static __device__ __forceinline__ void sp2(float a, float b, uint32_t& h, uint32_t& l) {
    uint32_t hp;
    asm("cvt.rn.bf16x2.f32 %0, %1, %2;" : "=r"(hp) : "f"(b), "f"(a));
    float ha = __uint_as_float(hp << 16);
    float hb = __uint_as_float(hp & 0xFFFF0000u);
    float la = a - ha;
    float lb = b - hb;
    uint32_t lp;
    asm("cvt.rn.bf16x2.f32 %0, %1, %2;" : "=r"(lp) : "f"(lb), "f"(la));
    h = hp; l = lp;
}

static __device__ __forceinline__ void ldsm4(uint32_t a, uint32_t* r) {
    asm volatile("ldmatrix.sync.aligned.m8n8.x4.shared.b16 {%0,%1,%2,%3}, [%4];"
        : "=r"(r[0]), "=r"(r[1]), "=r"(r[2]), "=r"(r[3]) : "r"(a));
}
static __device__ __forceinline__ void ldsm2(uint32_t a, uint32_t* r) {
    asm volatile("ldmatrix.sync.aligned.m8n8.x2.shared.b16 {%0,%1}, [%2];"
        : "=r"(r[0]), "=r"(r[1]) : "r"(a));
}
static __device__ __forceinline__ void ldsm1(uint32_t a, uint32_t* r) {
    asm volatile("ldmatrix.sync.aligned.m8n8.x1.shared.b16 {%0}, [%1];"
        : "=r"(r[0]) : "r"(a));
}
static __device__ __forceinline__ void mma16(float* c, const uint32_t* A, const uint32_t* B) {
    asm volatile("mma.sync.aligned.m16n8k16.row.col.f32.bf16.bf16.f32 "
        "{%0,%1,%2,%3}, {%4,%5,%6,%7}, {%8,%9}, {%0,%1,%2,%3};"
        : "+f"(c[0]), "+f"(c[1]), "+f"(c[2]), "+f"(c[3])
        : "r"(A[0]), "r"(A[1]), "r"(A[2]), "r"(A[3]), "r"(B[0]), "r"(B[1]));
}
static __device__ __forceinline__ void mma8(float* c, const uint32_t* A, uint32_t B) {
    asm volatile("mma.sync.aligned.m16n8k8.row.col.f32.bf16.bf16.f32 "
        "{%0,%1,%2,%3}, {%4,%5}, {%6}, {%0,%1,%2,%3};"
        : "+f"(c[0]), "+f"(c[1]), "+f"(c[2]), "+f"(c[3])
        : "r"(A[0]), "r"(A[1]), "r"(B));
}

struct Offs {
    uint32_t aoff;       // A k16 x4 base (frag f adds f*16*RSTR)
    uint32_t a8off;      // A k8 packed x4 base (frags 0,1; +32*RSTR for 2,3)
    uint32_t bpo[4];     // B x4 pair offsets (k16)
    uint32_t b16s;       // B x2 single-group offset (k16, last group, NG odd)
    uint32_t b8po[4];    // B x2 pair offsets (k8 tail)
    uint32_t b8s;        // B x1 single-group offset (k8 tail, NG odd)
};

// One k16 step: load A (4 frags, hi+lo) + B (NG groups, hi+lo), issue 3 products.
template<int NG>
static __device__ __forceinline__ void k16_step(
    int s, uint32_t yhb, uint32_t ylb, uint32_t whb, uint32_t wlb,
    const Offs& o, float (*acc)[4])
{
    const uint32_t kb = (uint32_t)s * 32;
    uint32_t Ah[4][4], Al[4][4];
    #pragma unroll
    for (int f = 0; f < 4; ++f) {
        ldsm4(yhb + o.aoff + f * (16 * RSTR) + kb, Ah[f]);
        ldsm4(ylb + o.aoff + f * (16 * RSTR) + kb, Al[f]);
    }
    uint32_t Bh[NG][2], Bl[NG][2];
    #pragma unroll
    for (int p = 0; p < NG / 2; ++p) {
        uint32_t r[4];
        ldsm4(whb + o.bpo[p] + kb, r);
        Bh[2*p][0] = r[0]; Bh[2*p][1] = r[1];
        Bh[2*p+1][0] = r[2]; Bh[2*p+1][1] = r[3];
        ldsm4(wlb + o.bpo[p] + kb, r);
        Bl[2*p][0] = r[0]; Bl[2*p][1] = r[1];
        Bl[2*p+1][0] = r[2]; Bl[2*p+1][1] = r[3];
    }
    if (NG & 1) {
        ldsm2(whb + o.b16s + kb, Bh[NG-1]);
        ldsm2(wlb + o.b16s + kb, Bl[NG-1]);
    }
    #pragma unroll
    for (int f = 0; f < 4; ++f) {
        #pragma unroll
        for (int g = 0; g < NG; ++g)
            mma16(acc[f * NG + g], Ah[f], Bh[g]);
    }
    #pragma unroll
    for (int f = 0; f < 4; ++f) {
        #pragma unroll
        for (int g = 0; g < NG; ++g)
            mma16(acc[f * NG + g], Ah[f], Bl[g]);
    }
    #pragma unroll
    for (int f = 0; f < 4; ++f) {
        #pragma unroll
        for (int g = 0; g < NG; ++g)
            mma16(acc[f * NG + g], Al[f], Bh[g]);
    }
}

template<int CW>
static __device__ __forceinline__ void compute_tile(
    uint32_t yhb, uint32_t ylb, uint32_t whb, uint32_t wlb,
    const Offs& o, const float* bs, float* b1s,
    float* __restrict__ a1, long long row0, long long n,
    int mrow, int qr, int qc)
{
    constexpr int NG = CW ? 8 : 9;
    constexpr int G0 = CW ? 9 : 0;

    float acc[4 * NG][4];
    #pragma unroll
    for (int i = 0; i < 4 * NG; ++i)
        #pragma unroll
        for (int j = 0; j < 4; ++j) acc[i][j] = 0.f;

    #pragma unroll
    for (int s = 0; s < 8; ++s)
        k16_step<NG>(s, yhb, ylb, whb, wlb, o, acc);

    // ---- k8 tail: k = 128..135 (packed 2 frags per x4) ----
    {
        uint32_t Ah[4][2], Al[4][2];
        {
            uint32_t r[4];
            ldsm4(yhb + o.a8off, r);
            Ah[0][0] = r[0]; Ah[0][1] = r[1]; Ah[1][0] = r[2]; Ah[1][1] = r[3];
            ldsm4(yhb + o.a8off + 32 * RSTR, r);
            Ah[2][0] = r[0]; Ah[2][1] = r[1]; Ah[3][0] = r[2]; Ah[3][1] = r[3];
            ldsm4(ylb + o.a8off, r);
            Al[0][0] = r[0]; Al[0][1] = r[1]; Al[1][0] = r[2]; Al[1][1] = r[3];
            ldsm4(ylb + o.a8off + 32 * RSTR, r);
            Al[2][0] = r[0]; Al[2][1] = r[1]; Al[3][0] = r[2]; Al[3][1] = r[3];
        }
        uint32_t B8h[NG], B8l[NG];
        #pragma unroll
        for (int p = 0; p < NG / 2; ++p) {
            uint32_t r[2];
            ldsm2(whb + o.b8po[p], r);
            B8h[2*p] = r[0]; B8h[2*p+1] = r[1];
            ldsm2(wlb + o.b8po[p], r);
            B8l[2*p] = r[0]; B8l[2*p+1] = r[1];
        }
        if (NG & 1) {
            uint32_t r[1];
            ldsm1(whb + o.b8s, r); B8h[NG-1] = r[0];
            ldsm1(wlb + o.b8s, r); B8l[NG-1] = r[0];
        }
        #pragma unroll
        for (int f = 0; f < 4; ++f) {
            #pragma unroll
            for (int g = 0; g < NG; ++g) {
                mma8(acc[f * NG + g], Ah[f], B8h[g]);
                mma8(acc[f * NG + g], Ah[f], B8l[g]);
                mma8(acc[f * NG + g], Al[f], B8h[g]);
            }
        }
    }

    // ---- epilogue ----
    #pragma unroll
    for (int f = 0; f < 4; ++f) {
        #pragma unroll
        for (int g = 0; g < NG; ++g) {
            const int ga = G0 + g;
            const float* ac = acc[f * NG + g];
            const int colg = ga * 8 + qc * 2;
            if (ga < 16) {
                float bx = bs[colg], by = bs[colg + 1];
                long long r1 = row0 + mrow + f * 16 + qr;
                if (r1 < n)
                    *(float2*)(a1 + r1 * FDIM + colg) = make_float2(ac[0] + bx, ac[1] + by);
                if (r1 + 8 < n)
                    *(float2*)(a1 + (r1 + 8) * FDIM + colg) = make_float2(ac[2] + bx, ac[3] + by);
            } else if (ga == 16) {
                if (qc < 2) {
                    int l = qc * 2;
                    float bx = bs[FDIM + l], by = bs[FDIM + l + 1];
                    int rl = mrow + f * 16 + qr;
                    b1s[rl * 4 + l]       = ac[0] + bx;
                    b1s[rl * 4 + l + 1]   = ac[1] + by;
                    b1s[(rl + 8) * 4 + l]     = ac[2] + bx;
                    b1s[(rl + 8) * 4 + l + 1] = ac[3] + by;
                }
            }
        }
    }
}

// ---- staging: warp w covers rows [w*32, w*32+32), lane covers cols lane*4..lane*4+3 ----
static __device__ __forceinline__ void stage_x(
    const float* __restrict__ x, char* sm, long long row0, long long n,
    int wid, int lane)
{
    #pragma unroll 4
    for (int i = 0; i < 32; ++i) {
        int rloc = wid * 32 + i;
        long long row = row0 + rloc;
        float4 v = (row < n) ? *(const float4*)(x + row * FDIM + lane * 4)
                             : make_float4(0.f, 0.f, 0.f, 0.f);
        uint2 hv, lv;
        sp2(v.x, v.y, hv.x, lv.x);
        sp2(v.z, v.w, hv.y, lv.y);
        *(uint2*)(sm + SM_YH + rloc * RSTR + lane * 8) = hv;
        *(uint2*)(sm + SM_YL + rloc * RSTR + lane * 8) = lv;
    }
}

// ---- d_chi: thread tid covers row tid entirely (no shfl) ----
static __device__ __forceinline__ void stage_dchi(
    const float* __restrict__ chi, char* sm, long long row, bool ok, int rloc)
{
    float c[16];
    #pragma unroll
    for (int q = 0; q < 4; ++q) {
        float4 v = ok ? *(const float4*)(chi + row * 16 + q * 4)
                      : make_float4(0.f, 0.f, 0.f, 0.f);
        c[q*4+0] = v.x; c[q*4+1] = v.y; c[q*4+2] = v.z; c[q*4+3] = v.w;
    }
    float s0 = c[0] * c[0];
    float s1 = c[1]*c[1] + c[2]*c[2] + c[3]*c[3];
    float s2 = 0.f, s3 = 0.f;
    #pragma unroll
    for (int m = 4; m < 9; ++m)  s2 += c[m] * c[m];
    #pragma unroll
    for (int m = 9; m < 16; ++m) s3 += c[m] * c[m];
    uint32_t h0, l0, h1, l1;
    sp2(s0, s1, h0, l0);
    sp2(s2, s3, h1, l1);
    *(uint4*)(sm + SM_YH + rloc * RSTR + 256) = make_uint4(h0, h1, 0u, 0u);
    *(uint4*)(sm + SM_YL + rloc * RSTR + 256) = make_uint4(l0, l1, 0u, 0u);
}

// ---- chi_out: thread tid covers row tid; reloads chi (L2-warm) ----
static __device__ __forceinline__ void chi_out_store(
    float* __restrict__ co, const float* __restrict__ chi, const float* b1s,
    long long row, bool ok, int rloc)
{
    if (!ok) return;
    float4 bv = ((const float4*)b1s)[rloc];
    float c[16];
    #pragma unroll
    for (int q = 0; q < 4; ++q) {
        float4 v = *(const float4*)(chi + row * 16 + q * 4);
        c[q*4+0] = v.x; c[q*4+1] = v.y; c[q*4+2] = v.z; c[q*4+3] = v.w;
    }
    float o8[16];
    o8[0] = bv.x * c[0];
    #pragma unroll
    for (int m = 1; m < 4; ++m)  o8[m] = bv.y * c[m];
    #pragma unroll
    for (int m = 4; m < 9; ++m)  o8[m] = bv.z * c[m];
    #pragma unroll
    for (int m = 9; m < 16; ++m) o8[m] = bv.w * c[m];
    float4* dst = (float4*)(co + row * 16);
    #pragma unroll
    for (int q = 0; q < 4; ++q)
        dst[q] = make_float4(o8[q*4], o8[q*4+1], o8[q*4+2], o8[q*4+3]);
}

__global__ void __launch_bounds__(NTHR, 1)
ib_mma(const float* __restrict__ x, const float* __restrict__ chi,
       const float* __restrict__ W, const float* __restrict__ b,
       float* __restrict__ a1, float* __restrict__ co,
       long long n, long long T)
{
    extern __shared__ char sm[];
    float* bs  = (float*)(sm + SM_BS);
    float* b1s = (float*)(sm + SM_B1S);
    unsigned short* whp = (unsigned short*)(sm + SM_WH);
    unsigned short* wlp = (unsigned short*)(sm + SM_WL);

    const int tid = threadIdx.x, wid = tid >> 5, lane = tid & 31;
    const uint32_t smb = smem_u32(sm);
    const uint32_t yhb = smb + SM_YH, ylb = smb + SM_YL;
    const uint32_t whb = smb + SM_WH, wlb = smb + SM_WL;

    // ---- stage W^T (hi/lo bf16) + bias, once ----
    for (int i = tid; i < KBE * KBE; i += NTHR) {
        int nn = i % KBE, kk = i / KBE;
        float w = (nn < CDIM && kk < CDIM) ? W[kk * CDIM + nn] : 0.f;
        unsigned short h, l;
        split(w, h, l);
        whp[nn * KBE + kk] = h;
        wlp[nn * KBE + kk] = l;
    }
    for (int i = tid; i < KBE; i += NTHR) bs[i] = (i < CDIM) ? b[i] : 0.f;

    // ---- per-warp ldmatrix offsets (4M x 2N warp grid, M=64/warp) ----
    const int mrow = (wid & 3) * 64;
    const int cw   = wid >> 2;               // 0: groups 0..8, 1: groups 9..16
    const int j3 = lane >> 3, rw = lane & 7;
    const int qr = lane >> 2, qc = lane & 3;
    const int g0 = cw ? 9 : 0;

    Offs o;
    o.aoff  = (uint32_t)((mrow + ((j3 & 1) << 3) + rw) * RSTR + ((j3 >> 1) << 4));
    o.a8off = (uint32_t)((mrow + j3 * 8 + rw) * RSTR + 256);
    #pragma unroll
    for (int p = 0; p < 4; ++p) {
        int g = g0 + 2 * p;
        o.bpo[p]  = (uint32_t)((g * 8 + ((j3 >> 1) << 3) + rw) * RSTR + ((j3 & 1) << 4));
        o.b8po[p] = (uint32_t)((g * 8 + ((j3 & 1) << 3) + rw) * RSTR + 256);
    }
    o.b16s = (uint32_t)((64 + rw) * RSTR + ((j3 & 1) << 4));
    o.b8s  = (uint32_t)((64 + rw) * RSTR + 256);

    const int grid = gridDim.x;

    // ---- preamble: stage first tile ----
    {
        long long row0 = blockIdx.x * (long long)TILE;
        stage_x(x, sm, row0, n, wid, lane);
        stage_dchi(chi, sm, row0 + tid, row0 + tid < n, tid);
    }
    __syncthreads();

    for (long long t = blockIdx.x; t < T; t += grid) {
        const long long row0 = t * TILE;

        // ---- MMA + a1/b1 epilogue ----
        if (cw == 0)
            compute_tile<0>(yhb, ylb, whb, wlb, o, bs, b1s, a1, row0, n, mrow, qr, qc);
        else
            compute_tile<1>(yhb, ylb, whb, wlb, o, bs, b1s, a1, row0, n, mrow, qr, qc);
        __syncthreads();

        // ---- stage(t+grid) + chi_out(t) in one phase ----
        const long long t2 = t + grid;
        if (t2 < T) {
            long long r2 = t2 * TILE;
            stage_x(x, sm, r2, n, wid, lane);
            stage_dchi(chi, sm, r2 + tid, r2 + tid < n, tid);
        }
        chi_out_store(co, chi, b1s, row0 + tid, row0 + tid < n, tid);
        __syncthreads();
    }
}

extern "C" void kernel_launch(void* const* d_in, const int* in_sizes, int n_in,
                              void* d_out, int out_size)
{
    int ix = 0, ichi = 1, iW = 3, ib_ = 4;
    long long maxsz = -1;
    for (int i = 0; i < n_in; ++i)
        if ((long long)in_sizes[i] > maxsz) { maxsz = in_sizes[i]; ix = i; }
    long long n = maxsz / FDIM;
    for (int i = 0; i < n_in; ++i) {
        long long s = in_sizes[i];
        if (i == ix) continue;
        if (s == CDIM * CDIM) iW = i;
        else if (s == CDIM)   ib_ = i;
        else if (s == 16 * n) ichi = i;
    }
    const float* x   = (const float*)d_in[ix];
    const float* chi = (const float*)d_in[ichi];
    const float* W   = (const float*)d_in[iW];
    const float* b   = (const float*)d_in[ib_];
    float* a1 = (float*)d_out;
    float* co = a1 + (size_t)n * FDIM;

    long long T = (n + TILE - 1) / TILE;
    int sms = 148;
    cudaDeviceGetAttribute(&sms, cudaDevAttrMultiProcessorCount, 0);
    int grid = (int)(T < sms ? T : sms);

    cudaFuncSetAttribute(ib_mma, cudaFuncAttributeMaxDynamicSharedMemorySize, SMEM_BYTES);
    ib_mma<<<grid, NTHR, SMEM_BYTES>>>(x, chi, W, b, a1, co, n, T);
}

// round 13
// speedup vs baseline: 1.2512x; 1.1647x over previous
#include <cuda_runtime.h>
#include <cuda_bf16.h>
#include <cstdint>

#define FDIM 128
#define CDIM 132
#define KBE  136          // padded K in bf16 elements
#define RSTR 272          // bytes per smem row of W (136 bf16)
#define TILE 256
#define NTHR 256

// smem byte offsets
#define SM_BS   0                           // bias: 136 floats
#define SM_B1S  1024                        // b1 double buffer: 2 x 4096
#define SM_DH   9216                        // d_chi hi double buffer: 2 x 4096 (256 rows x 16B)
#define SM_DL   17408                       // d_chi lo double buffer: 2 x 4096
#define SM_WH   25600
#define SM_WL   (SM_WH + KBE * RSTR)        // 62592
#define SMEM_BYTES (SM_WL + KBE * RSTR)     // 99584

static __device__ __forceinline__ uint32_t smem_u32(const void* p) {
    uint32_t a;
    asm("{ .reg .u64 t; cvta.to.shared.u64 t, %1; cvt.u32.u64 %0, t; }" : "=r"(a) : "l"(p));
    return a;
}
static __device__ __forceinline__ void split(float v, unsigned short& h, unsigned short& l) {
    __nv_bfloat16 hb = __float2bfloat16(v);
    float r = v - __bfloat162float(hb);
    __nv_bfloat16 lb = __float2bfloat16(r);
    h = __bfloat16_as_ushort(hb);
    l = __bfloat16_as_ushort(lb);
}
// packed split: a -> lower half, b -> upper half
static __device__ __forceinline__ void sp2(float a, float b, uint32_t& h, uint32_t& l) {
    uint32_t hp;
    asm("cvt.rn.bf16x2.f32 %0, %1, %2;" : "=r"(hp) : "f"(b), "f"(a));
    float ha = __uint_as_float(hp << 16);
    float hb = __uint_as_float(hp & 0xFFFF0000u);
    float la = a - ha;
    float lb = b - hb;
    uint32_t lp;
    asm("cvt.rn.bf16x2.f32 %0, %1, %2;" : "=r"(lp) : "f"(lb), "f"(la));
    h = hp; l = lp;
}

static __device__ __forceinline__ void ldsm4(uint32_t a, uint32_t* r) {
    asm volatile("ldmatrix.sync.aligned.m8n8.x4.shared.b16 {%0,%1,%2,%3}, [%4];"
        : "=r"(r[0]), "=r"(r[1]), "=r"(r[2]), "=r"(r[3]) : "r"(a));
}
static __device__ __forceinline__ void ldsm2(uint32_t a, uint32_t* r) {
    asm volatile("ldmatrix.sync.aligned.m8n8.x2.shared.b16 {%0,%1}, [%2];"
        : "=r"(r[0]), "=r"(r[1]) : "r"(a));
}
static __device__ __forceinline__ void ldsm1(uint32_t a, uint32_t* r) {
    asm volatile("ldmatrix.sync.aligned.m8n8.x1.shared.b16 {%0}, [%1];"
        : "=r"(r[0]) : "r"(a));
}
static __device__ __forceinline__ void mma16(float* c, const uint32_t* A, const uint32_t* B) {
    asm volatile("mma.sync.aligned.m16n8k16.row.col.f32.bf16.bf16.f32 "
        "{%0,%1,%2,%3}, {%4,%5,%6,%7}, {%8,%9}, {%0,%1,%2,%3};"
        : "+f"(c[0]), "+f"(c[1]), "+f"(c[2]), "+f"(c[3])
        : "r"(A[0]), "r"(A[1]), "r"(A[2]), "r"(A[3]), "r"(B[0]), "r"(B[1]));
}
static __device__ __forceinline__ void mma8(float* c, const uint32_t* A, uint32_t B) {
    asm volatile("mma.sync.aligned.m16n8k8.row.col.f32.bf16.bf16.f32 "
        "{%0,%1,%2,%3}, {%4,%5}, {%6}, {%0,%1,%2,%3};"
        : "+f"(c[0]), "+f"(c[1]), "+f"(c[2]), "+f"(c[3])
        : "r"(A[0]), "r"(A[1]), "r"(B));
}

struct Offs {
    uint32_t bpo[4];     // B x4 pair offsets (k16)
    uint32_t b16s;       // B x2 single-group offset (NG odd)
    uint32_t b8po[4];    // B x2 pair offsets (k8 tail)
    uint32_t b8s;        // B x1 single-group offset (k8 tail, NG odd)
};
struct ARow { const float* p[8]; };  // clamped row pointers: [frag f][half h]

// One k16 step: A direct from global (float2 loads + inline hi/lo split),
// B via ldmatrix from W smem; 3 products (hi*hi + hi*lo + lo*hi).
template<int NG>
static __device__ __forceinline__ void k16_step(
    int s, const ARow& ar, uint32_t whb, uint32_t wlb,
    const Offs& o, float (*acc)[4])
{
    const uint32_t kb = (uint32_t)s * 32;
    const int xo = s * 16;
    float2 raw[4][4];
    #pragma unroll
    for (int f = 0; f < 4; ++f) {
        raw[f][0] = *(const float2*)(ar.p[2*f]   + xo);
        raw[f][1] = *(const float2*)(ar.p[2*f+1] + xo);
        raw[f][2] = *(const float2*)(ar.p[2*f]   + xo + 8);
        raw[f][3] = *(const float2*)(ar.p[2*f+1] + xo + 8);
    }
    uint32_t Bh[NG][2], Bl[NG][2];
    #pragma unroll
    for (int p = 0; p < NG / 2; ++p) {
        uint32_t r[4];
        ldsm4(whb + o.bpo[p] + kb, r);
        Bh[2*p][0] = r[0]; Bh[2*p][1] = r[1];
        Bh[2*p+1][0] = r[2]; Bh[2*p+1][1] = r[3];
        ldsm4(wlb + o.bpo[p] + kb, r);
        Bl[2*p][0] = r[0]; Bl[2*p][1] = r[1];
        Bl[2*p+1][0] = r[2]; Bl[2*p+1][1] = r[3];
    }
    if (NG & 1) {
        ldsm2(whb + o.b16s + kb, Bh[NG-1]);
        ldsm2(wlb + o.b16s + kb, Bl[NG-1]);
    }
    uint32_t Ah[4][4], Al[4][4];
    #pragma unroll
    for (int f = 0; f < 4; ++f)
        #pragma unroll
        for (int j = 0; j < 4; ++j)
            sp2(raw[f][j].x, raw[f][j].y, Ah[f][j], Al[f][j]);
    #pragma unroll
    for (int f = 0; f < 4; ++f)
        #pragma unroll
        for (int g = 0; g < NG; ++g)
            mma16(acc[f * NG + g], Ah[f], Bh[g]);
    #pragma unroll
    for (int f = 0; f < 4; ++f)
        #pragma unroll
        for (int g = 0; g < NG; ++g)
            mma16(acc[f * NG + g], Ah[f], Bl[g]);
    #pragma unroll
    for (int f = 0; f < 4; ++f)
        #pragma unroll
        for (int g = 0; g < NG; ++g)
            mma16(acc[f * NG + g], Al[f], Bh[g]);
}

template<int CW>
static __device__ __forceinline__ void compute_tile(
    const ARow& ar, const char* smc, uint32_t dhoff, uint32_t dloff,
    uint32_t whb, uint32_t wlb, const Offs& o, const float* bs, float* b1s,
    float* __restrict__ a1, long long row0, long long n,
    int mrow, int qr, int qc)
{
    constexpr int NG = CW ? 8 : 9;
    constexpr int G0 = CW ? 9 : 0;

    float acc[4 * NG][4];
    #pragma unroll
    for (int i = 0; i < 4 * NG; ++i)
        #pragma unroll
        for (int j = 0; j < 4; ++j) acc[i][j] = 0.f;

    #pragma unroll
    for (int s = 0; s < 8; ++s)
        k16_step<NG>(s, ar, whb, wlb, o, acc);

    // ---- k8 tail: k = 128..135, A from d_chi smem ----
    {
        uint32_t Ah[4][2], Al[4][2];
        const uint32_t db = (uint32_t)((mrow + qr) * 16 + qc * 4);
        #pragma unroll
        for (int f = 0; f < 4; ++f) {
            Ah[f][0] = *(const uint32_t*)(smc + dhoff + db + f * 256);
            Ah[f][1] = *(const uint32_t*)(smc + dhoff + db + f * 256 + 128);
            Al[f][0] = *(const uint32_t*)(smc + dloff + db + f * 256);
            Al[f][1] = *(const uint32_t*)(smc + dloff + db + f * 256 + 128);
        }
        uint32_t B8h[NG], B8l[NG];
        #pragma unroll
        for (int p = 0; p < NG / 2; ++p) {
            uint32_t r[2];
            ldsm2(whb + o.b8po[p], r);
            B8h[2*p] = r[0]; B8h[2*p+1] = r[1];
            ldsm2(wlb + o.b8po[p], r);
            B8l[2*p] = r[0]; B8l[2*p+1] = r[1];
        }
        if (NG & 1) {
            uint32_t r[1];
            ldsm1(whb + o.b8s, r); B8h[NG-1] = r[0];
            ldsm1(wlb + o.b8s, r); B8l[NG-1] = r[0];
        }
        #pragma unroll
        for (int f = 0; f < 4; ++f) {
            #pragma unroll
            for (int g = 0; g < NG; ++g) {
                mma8(acc[f * NG + g], Ah[f], B8h[g]);
                mma8(acc[f * NG + g], Ah[f], B8l[g]);
                mma8(acc[f * NG + g], Al[f], B8h[g]);
            }
        }
    }

    // ---- epilogue ----
    #pragma unroll
    for (int f = 0; f < 4; ++f) {
        #pragma unroll
        for (int g = 0; g < NG; ++g) {
            const int ga = G0 + g;
            const float* ac = acc[f * NG + g];
            const int colg = ga * 8 + qc * 2;
            if (ga < 16) {
                float bx = bs[colg], by = bs[colg + 1];
                long long r1 = row0 + mrow + f * 16 + qr;
                if (r1 < n)
                    *(float2*)(a1 + r1 * FDIM + colg) = make_float2(ac[0] + bx, ac[1] + by);
                if (r1 + 8 < n)
                    *(float2*)(a1 + (r1 + 8) * FDIM + colg) = make_float2(ac[2] + bx, ac[3] + by);
            } else if (ga == 16) {
                if (qc < 2) {
                    int l = qc * 2;
                    float bx = bs[FDIM + l], by = bs[FDIM + l + 1];
                    int rl = mrow + f * 16 + qr;
                    b1s[rl * 4 + l]       = ac[0] + bx;
                    b1s[rl * 4 + l + 1]   = ac[1] + by;
                    b1s[(rl + 8) * 4 + l]     = ac[2] + bx;
                    b1s[(rl + 8) * 4 + l + 1] = ac[3] + by;
                }
            }
        }
    }
}

// ---- d_chi staging: thread tid covers row tid (no shfl); zero-padded cols 4..7 ----
static __device__ __forceinline__ void stage_dchi(
    const float* __restrict__ chi, char* sm, uint32_t dhoff, uint32_t dloff,
    long long row, bool ok, int rloc)
{
    float c[16];
    #pragma unroll
    for (int q = 0; q < 4; ++q) {
        float4 v = ok ? *(const float4*)(chi + row * 16 + q * 4)
                      : make_float4(0.f, 0.f, 0.f, 0.f);
        c[q*4+0] = v.x; c[q*4+1] = v.y; c[q*4+2] = v.z; c[q*4+3] = v.w;
    }
    float s0 = c[0] * c[0];
    float s1 = c[1]*c[1] + c[2]*c[2] + c[3]*c[3];
    float s2 = 0.f, s3 = 0.f;
    #pragma unroll
    for (int m = 4; m < 9; ++m)  s2 += c[m] * c[m];
    #pragma unroll
    for (int m = 9; m < 16; ++m) s3 += c[m] * c[m];
    uint32_t h0, l0, h1, l1;
    sp2(s0, s1, h0, l0);
    sp2(s2, s3, h1, l1);
    *(uint4*)(sm + dhoff + rloc * 16) = make_uint4(h0, h1, 0u, 0u);
    *(uint4*)(sm + dloff + rloc * 16) = make_uint4(l0, l1, 0u, 0u);
}

// ---- chi_out: thread tid covers row tid; reloads chi (L2-warm) ----
static __device__ __forceinline__ void chi_out_store(
    float* __restrict__ co, const float* __restrict__ chi, const float* b1s,
    long long row, bool ok, int rloc)
{
    if (!ok) return;
    float4 bv = ((const float4*)b1s)[rloc];
    float c[16];
    #pragma unroll
    for (int q = 0; q < 4; ++q) {
        float4 v = *(const float4*)(chi + row * 16 + q * 4);
        c[q*4+0] = v.x; c[q*4+1] = v.y; c[q*4+2] = v.z; c[q*4+3] = v.w;
    }
    float o8[16];
    o8[0] = bv.x * c[0];
    #pragma unroll
    for (int m = 1; m < 4; ++m)  o8[m] = bv.y * c[m];
    #pragma unroll
    for (int m = 4; m < 9; ++m)  o8[m] = bv.z * c[m];
    #pragma unroll
    for (int m = 9; m < 16; ++m) o8[m] = bv.w * c[m];
    float4* dst = (float4*)(co + row * 16);
    #pragma unroll
    for (int q = 0; q < 4; ++q)
        dst[q] = make_float4(o8[q*4], o8[q*4+1], o8[q*4+2], o8[q*4+3]);
}

__global__ void __launch_bounds__(NTHR, 1)
ib_mma(const float* __restrict__ x, const float* __restrict__ chi,
       const float* __restrict__ W, const float* __restrict__ b,
       float* __restrict__ a1, float* __restrict__ co,
       long long n, long long T)
{
    extern __shared__ char sm[];
    float* bs = (float*)(sm + SM_BS);
    unsigned short* whp = (unsigned short*)(sm + SM_WH);
    unsigned short* wlp = (unsigned short*)(sm + SM_WL);

    const int tid = threadIdx.x, wid = tid >> 5, lane = tid & 31;
    const uint32_t smb = smem_u32(sm);
    const uint32_t whb = smb + SM_WH, wlb = smb + SM_WL;

    // ---- stage W^T (hi/lo bf16) + bias, once ----
    for (int i = tid; i < KBE * KBE; i += NTHR) {
        int nn = i % KBE, kk = i / KBE;
        float w = (nn < CDIM && kk < CDIM) ? W[kk * CDIM + nn] : 0.f;
        unsigned short h, l;
        split(w, h, l);
        whp[nn * KBE + kk] = h;
        wlp[nn * KBE + kk] = l;
    }
    for (int i = tid; i < KBE; i += NTHR) bs[i] = (i < CDIM) ? b[i] : 0.f;

    // ---- per-warp layout (4M x 2N grid, M=64/warp) ----
    const int mrow = (wid & 3) * 64;
    const int cw   = wid >> 2;
    const int j3 = lane >> 3, rw = lane & 7;
    const int qr = lane >> 2, qc = lane & 3;
    const int g0 = cw ? 9 : 0;

    Offs o;
    #pragma unroll
    for (int p = 0; p < 4; ++p) {
        int g = g0 + 2 * p;
        o.bpo[p]  = (uint32_t)((g * 8 + ((j3 >> 1) << 3) + rw) * RSTR + ((j3 & 1) << 4));
        o.b8po[p] = (uint32_t)((g * 8 + ((j3 & 1) << 3) + rw) * RSTR + 256);
    }
    o.b16s = (uint32_t)((64 + rw) * RSTR + ((j3 & 1) << 4));
    o.b8s  = (uint32_t)((64 + rw) * RSTR + 256);

    const int grid = gridDim.x;

    // ---- preamble: d_chi for first tile into buf 0 ----
    {
        long long row = blockIdx.x * (long long)TILE + tid;
        stage_dchi(chi, sm, SM_DH, SM_DL, row, (blockIdx.x < T) && (row < n), tid);
    }
    __syncthreads();

    int p = 0;
    for (long long t = blockIdx.x; t < T; t += grid) {
        const long long row0 = t * TILE;
        const uint32_t dh = SM_DH + (uint32_t)p * 4096;
        const uint32_t dl = SM_DL + (uint32_t)p * 4096;
        float* b1s_p = (float*)(sm + SM_B1S + p * 4096);

        // clamped A row pointers (garbage rows are never stored)
        ARow ar;
        #pragma unroll
        for (int f = 0; f < 4; ++f)
            #pragma unroll
            for (int h = 0; h < 2; ++h) {
                long long r = row0 + mrow + f * 16 + h * 8 + qr;
                if (r > n - 1) r = n - 1;
                ar.p[f * 2 + h] = x + r * FDIM + 2 * qc;
            }

        // ---- MMA (A streamed from global) + a1/b1 epilogue ----
        if (cw == 0)
            compute_tile<0>(ar, sm, dh, dl, whb, wlb, o, bs, b1s_p,
                            a1, row0, n, mrow, qr, qc);
        else
            compute_tile<1>(ar, sm, dh, dl, whb, wlb, o, bs, b1s_p,
                            a1, row0, n, mrow, qr, qc);

        // ---- per-warp: d_chi(t+grid) into buf p^1 (no sync needed) ----
        const long long t2 = t + grid;
        if (t2 < T) {
            long long row2 = t2 * TILE + tid;
            stage_dchi(chi, sm, SM_DH + (uint32_t)(p ^ 1) * 4096,
                       SM_DL + (uint32_t)(p ^ 1) * 4096, row2, row2 < n, tid);
        }
        __syncthreads();   // b1s[p] + dchi[p^1] ready

        // ---- chi_out(t); overlaps next tile's compute in other warps ----
        chi_out_store(co, chi, b1s_p, row0 + tid, row0 + tid < n, tid);
        p ^= 1;
    }
}

extern "C" void kernel_launch(void* const* d_in, const int* in_sizes, int n_in,
                              void* d_out, int out_size)
{
    int ix = 0, ichi = 1, iW = 3, ib_ = 4;
    long long maxsz = -1;
    for (int i = 0; i < n_in; ++i)
        if ((long long)in_sizes[i] > maxsz) { maxsz = in_sizes[i]; ix = i; }
    long long n = maxsz / FDIM;
    for (int i = 0; i < n_in; ++i) {
        long long s = in_sizes[i];
        if (i == ix) continue;
        if (s == CDIM * CDIM) iW = i;
        else if (s == CDIM)   ib_ = i;
        else if (s == 16 * n) ichi = i;
    }
    const float* x   = (const float*)d_in[ix];
    const float* chi = (const float*)d_in[ichi];
    const float* W   = (const float*)d_in[iW];
    const float* b   = (const float*)d_in[ib_];
    float* a1 = (float*)d_out;
    float* co = a1 + (size_t)n * FDIM;

    long long T = (n + TILE - 1) / TILE;
    int sms = 148;
    cudaDeviceGetAttribute(&sms, cudaDevAttrMultiProcessorCount, 0);
    int grid = (int)(T < sms ? T : sms);

    cudaFuncSetAttribute(ib_mma, cudaFuncAttributeMaxDynamicSharedMemorySize, SMEM_BYTES);
    ib_mma<<<grid, NTHR, SMEM_BYTES>>>(x, chi, W, b, a1, co, n, T);
}